// round 1
// baseline (speedup 1.0000x reference)
#include <cuda_runtime.h>
#include <math.h>

// ---------------- constants ----------------
#define MROWS  100352      // 32 * 3136
#define CDIM   192
#define NHEADS 6
#define KD     32
#define QKVN   576
#define HID    768
#define HW     56

// ---------------- scratch (device globals; no cudaMalloc allowed) ----------------
__device__ float g_ln  [(size_t)MROWS * CDIM];   //  77 MB (LN1 out, reused for LN2 out)
__device__ float g_qkv [(size_t)MROWS * QKVN];   // 231 MB
__device__ float g_attn[(size_t)MROWS * CDIM];   //  77 MB
__device__ float g_x1  [(size_t)MROWS * CDIM];   //  77 MB (x + proj(attn))
__device__ float g_x2  [(size_t)MROWS * CDIM];   //  77 MB (conv+bn out)
__device__ float g_mlp [(size_t)MROWS * HID];    // 308 MB

// ---------------- LayerNorm: one warp per 192-wide row ----------------
__global__ void __launch_bounds__(256) ln_kernel(const float* __restrict__ x,
                                                 const float* __restrict__ g,
                                                 const float* __restrict__ b,
                                                 float* __restrict__ out)
{
    int warp = threadIdx.x >> 5;
    int lane = threadIdx.x & 31;
    long row = (long)blockIdx.x * 8 + warp;
    const float* xr = x + row * CDIM;

    float v[6];
#pragma unroll
    for (int i = 0; i < 6; i++) v[i] = xr[lane + 32 * i];

    float s = 0.f;
#pragma unroll
    for (int i = 0; i < 6; i++) s += v[i];
#pragma unroll
    for (int o = 16; o > 0; o >>= 1) s += __shfl_xor_sync(0xffffffffu, s, o);
    float mean = s * (1.0f / 192.0f);

    float sq = 0.f;
#pragma unroll
    for (int i = 0; i < 6; i++) { float d = v[i] - mean; sq += d * d; }
#pragma unroll
    for (int o = 16; o > 0; o >>= 1) sq += __shfl_xor_sync(0xffffffffu, sq, o);
    float rstd = rsqrtf(sq * (1.0f / 192.0f) + 1e-5f);

    float* orow = out + row * CDIM;
#pragma unroll
    for (int i = 0; i < 6; i++) {
        int c = lane + 32 * i;
        orow[c] = (v[i] - mean) * rstd * g[c] + b[c];
    }
}

// ---------------- GEMM: C[M,N] = A[M,K] @ B[K,N] + bias (+ epilogue) ----------------
// BM=128, BN=64, BK=16, 256 threads, 8x4 micro-tile per thread.
// EPI: 0 = bias only, 1 = bias + exact GELU, 2 = bias + residual add (res has same N)
template <int EPI>
__global__ void __launch_bounds__(256) gemm_kernel(const float* __restrict__ A,
                                                   const float* __restrict__ B,
                                                   const float* __restrict__ bias,
                                                   const float* __restrict__ res,
                                                   float* __restrict__ C,
                                                   int N, int K)
{
    const int BM = 128, BN = 64, BK = 16;
    __shared__ float As[BK * BM];
    __shared__ float Bs[BK * BN];

    int tid = threadIdx.x;
    int tx = tid & 15;          // 0..15 -> 4 cols each
    int ty = tid >> 4;          // 0..15 -> 8 rows each
    long m0 = (long)blockIdx.x * BM;
    int  n0 = blockIdx.y * BN;

    float acc[8][4];
#pragma unroll
    for (int i = 0; i < 8; i++)
#pragma unroll
        for (int j = 0; j < 4; j++) acc[i][j] = 0.f;

    for (int k0 = 0; k0 < K; k0 += BK) {
        // load A tile (128x16), store transposed As[kk][m]
#pragma unroll
        for (int r = 0; r < 2; r++) {
            int idx = tid + r * 256;          // 0..511
            int m  = idx >> 2;                // 0..127
            int kv = (idx & 3) * 4;           // 0,4,8,12
            float4 a = *(const float4*)(A + (m0 + m) * (long)K + k0 + kv);
            As[(kv + 0) * BM + m] = a.x;
            As[(kv + 1) * BM + m] = a.y;
            As[(kv + 2) * BM + m] = a.z;
            As[(kv + 3) * BM + m] = a.w;
        }
        // load B tile (16x64)
        {
            int kk = tid >> 4;                // 0..15
            int nv = (tid & 15) * 4;          // 0..60
            *(float4*)(Bs + kk * BN + nv) =
                *(const float4*)(B + (long)(k0 + kk) * N + n0 + nv);
        }
        __syncthreads();

#pragma unroll
        for (int kk = 0; kk < BK; kk++) {
            float4 a0 = *(const float4*)(As + kk * BM + ty * 8);
            float4 a1 = *(const float4*)(As + kk * BM + ty * 8 + 4);
            float4 bb = *(const float4*)(Bs + kk * BN + tx * 4);
            float av[8] = {a0.x, a0.y, a0.z, a0.w, a1.x, a1.y, a1.z, a1.w};
            float bv[4] = {bb.x, bb.y, bb.z, bb.w};
#pragma unroll
            for (int i = 0; i < 8; i++)
#pragma unroll
                for (int j = 0; j < 4; j++) acc[i][j] += av[i] * bv[j];
        }
        __syncthreads();
    }

    float4 bq = *(const float4*)(bias + n0 + tx * 4);
    float bv[4] = {bq.x, bq.y, bq.z, bq.w};

#pragma unroll
    for (int i = 0; i < 8; i++) {
        long m = m0 + ty * 8 + i;
        float o[4];
#pragma unroll
        for (int j = 0; j < 4; j++) o[j] = acc[i][j] + bv[j];
        if (EPI == 1) {
#pragma unroll
            for (int j = 0; j < 4; j++)
                o[j] = 0.5f * o[j] * (1.0f + erff(o[j] * 0.7071067811865476f));
        }
        if (EPI == 2) {
            float4 rq = *(const float4*)(res + m * N + n0 + tx * 4);
            o[0] += rq.x; o[1] += rq.y; o[2] += rq.z; o[3] += rq.w;
        }
        float4 oq = make_float4(o[0], o[1], o[2], o[3]);
        *(float4*)(C + m * N + n0 + tx * 4) = oq;
    }
}

// ---------------- Windowed attention: one block per (window, head) ----------------
// N=49 tokens, d=32. Gathers QKV rows via window map, scatters output rows.
__global__ void __launch_bounds__(128) attn_kernel(const float* __restrict__ attn_bias)
{
    __shared__ float qs[49 * 33];
    __shared__ float ks[49 * 33];
    __shared__ float vs[49 * 33];
    __shared__ float S[49 * 49];
    __shared__ float bh[49];
    __shared__ int   grow[49];

    int tid = threadIdx.x;
    int wid = blockIdx.x;            // 0..2047
    int h   = blockIdx.y;            // 0..5
    int b   = wid >> 6;
    int wr  = wid & 63;
    int wy  = wr >> 3, wx = wr & 7;

    if (tid < 49) {
        int ty = tid / 7, tx = tid - ty * 7;
        grow[tid] = b * 3136 + (wy * 7 + ty) * HW + (wx * 7 + tx);
        bh[tid]   = attn_bias[h * 49 + tid];
    }
    __syncthreads();

    for (int i = tid; i < 49 * 32; i += 128) {
        int t = i >> 5, d = i & 31;
        const float* p = g_qkv + (long)grow[t] * QKVN + h * 96 + d;
        qs[t * 33 + d] = p[0];
        ks[t * 33 + d] = p[32];
        vs[t * 33 + d] = p[64];
    }
    __syncthreads();

    const float scale = 0.17677669529663687f;   // 1/sqrt(32)
    for (int i = tid; i < 2401; i += 128) {
        int n = i / 49, m = i - n * 49;
        float s = 0.f;
#pragma unroll
        for (int d = 0; d < 32; d++) s += qs[n * 33 + d] * ks[m * 33 + d];
        int rn = n / 7, cn = n - rn * 7;
        int rm = m / 7, cm = m - rm * 7;
        int off = abs(rn - rm) * 7 + abs(cn - cm);
        S[i] = s * scale + bh[off];
    }
    __syncthreads();

    if (tid < 49) {
        float mx = -1e30f;
        for (int m = 0; m < 49; m++) mx = fmaxf(mx, S[tid * 49 + m]);
        float sum = 0.f;
        for (int m = 0; m < 49; m++) {
            float e = expf(S[tid * 49 + m] - mx);
            S[tid * 49 + m] = e;
            sum += e;
        }
        float inv = 1.0f / sum;
        for (int m = 0; m < 49; m++) S[tid * 49 + m] *= inv;
    }
    __syncthreads();

    for (int i = tid; i < 49 * 32; i += 128) {
        int n = i >> 5, d = i & 31;
        float s = 0.f;
#pragma unroll
        for (int m = 0; m < 49; m++) s += S[n * 49 + m] * vs[m * 33 + d];
        g_attn[(long)grow[n] * CDIM + h * KD + d] = s;
    }
}

// ---------------- depthwise 3x3 conv + BN (channels innermost -> coalesced) ----------------
__global__ void __launch_bounds__(192) dwconv_bn_kernel(const float* __restrict__ w,
                                                        const float* __restrict__ g,
                                                        const float* __restrict__ b,
                                                        const float* __restrict__ mean,
                                                        const float* __restrict__ var)
{
    int bl = blockIdx.x;           // 0..100351 = b*3136 + l
    int ch = threadIdx.x;          // 0..191
    int bb = bl / 3136;
    int l  = bl - bb * 3136;
    int r  = l / HW, c = l - r * HW;

    float acc = 0.f;
#pragma unroll
    for (int kh = 0; kh < 3; kh++) {
        int rr = r + kh - 1;
        if (rr < 0 || rr >= HW) continue;
#pragma unroll
        for (int kw = 0; kw < 3; kw++) {
            int cc = c + kw - 1;
            if (cc < 0 || cc >= HW) continue;
            acc += g_x1[((long)bb * 3136 + rr * HW + cc) * CDIM + ch] *
                   w[ch * 9 + kh * 3 + kw];
        }
    }
    float inv = rsqrtf(var[ch] + 1e-5f);
    g_x2[(long)bl * CDIM + ch] = (acc - mean[ch]) * g[ch] * inv + b[ch];
}

// ---------------- launch ----------------
extern "C" void kernel_launch(void* const* d_in, const int* in_sizes, int n_in,
                              void* d_out, int out_size)
{
    (void)in_sizes; (void)n_in; (void)out_size;
    const float* x        = (const float*)d_in[0];
    const float* norm1_g  = (const float*)d_in[1];
    const float* norm1_b  = (const float*)d_in[2];
    const float* qkv_w    = (const float*)d_in[3];
    const float* qkv_b    = (const float*)d_in[4];
    const float* attnbias = (const float*)d_in[5];
    const float* proj_w   = (const float*)d_in[6];
    const float* proj_b   = (const float*)d_in[7];
    const float* conv_w   = (const float*)d_in[8];
    const float* bn_g     = (const float*)d_in[9];
    const float* bn_b     = (const float*)d_in[10];
    const float* bn_mean  = (const float*)d_in[11];
    const float* bn_var   = (const float*)d_in[12];
    const float* norm2_g  = (const float*)d_in[13];
    const float* norm2_b  = (const float*)d_in[14];
    const float* fc1_w    = (const float*)d_in[15];
    const float* fc1_b    = (const float*)d_in[16];
    const float* fc2_w    = (const float*)d_in[17];
    const float* fc2_b    = (const float*)d_in[18];
    float* out = (float*)d_out;

    float *p_ln, *p_qkv, *p_attn, *p_x1, *p_x2, *p_mlp;
    cudaGetSymbolAddress((void**)&p_ln,   g_ln);
    cudaGetSymbolAddress((void**)&p_qkv,  g_qkv);
    cudaGetSymbolAddress((void**)&p_attn, g_attn);
    cudaGetSymbolAddress((void**)&p_x1,   g_x1);
    cudaGetSymbolAddress((void**)&p_x2,   g_x2);
    cudaGetSymbolAddress((void**)&p_mlp,  g_mlp);

    // 1) LN1
    ln_kernel<<<MROWS / 8, 256>>>(x, norm1_g, norm1_b, p_ln);
    // 2) QKV GEMM: [M,192] @ [192,576]
    gemm_kernel<0><<<dim3(MROWS / 128, QKVN / 64), 256>>>(p_ln, qkv_w, qkv_b, nullptr, p_qkv, QKVN, CDIM);
    // 3) windowed attention
    attn_kernel<<<dim3(2048, NHEADS), 128>>>(attnbias);
    // 4) proj GEMM + residual x
    gemm_kernel<2><<<dim3(MROWS / 128, CDIM / 64), 256>>>(p_attn, proj_w, proj_b, x, p_x1, CDIM, CDIM);
    // 5) depthwise conv + BN
    dwconv_bn_kernel<<<MROWS, CDIM>>>(conv_w, bn_g, bn_b, bn_mean, bn_var);
    // 6) LN2
    ln_kernel<<<MROWS / 8, 256>>>(p_x2, norm2_g, norm2_b, p_ln);
    // 7) fc1 GEMM + GELU: [M,192] @ [192,768]
    gemm_kernel<1><<<dim3(MROWS / 128, HID / 64), 256>>>(p_ln, fc1_w, fc1_b, nullptr, p_mlp, HID, CDIM);
    // 8) fc2 GEMM + residual x2 -> out: [M,768] @ [768,192]
    gemm_kernel<2><<<dim3(MROWS / 128, CDIM / 64), 256>>>(p_mlp, fc2_w, fc2_b, p_x2, out, CDIM, HID);
}

// round 2
// speedup vs baseline: 1.9227x; 1.9227x over previous
#include <cuda_runtime.h>
#include <math.h>
#include <stdint.h>

// ---------------- constants ----------------
#define MROWS  100352      // 32 * 3136
#define CDIM   192
#define NHEADS 6
#define KD     32
#define QKVN   576
#define HID    768
#define HW     56

// weight scratch offsets (tf32-rounded weights)
#define W_QKV  0
#define W_PROJ 110592
#define W_FC1  147456
#define W_FC2  294912
#define W_TOT  442368

// ---------------- scratch (device globals; no cudaMalloc allowed) ----------------
__device__ float g_ln  [(size_t)MROWS * CDIM];
__device__ float g_qkv [(size_t)MROWS * QKVN];
__device__ float g_attn[(size_t)MROWS * CDIM];
__device__ float g_x1  [(size_t)MROWS * CDIM];
__device__ float g_x2  [(size_t)MROWS * CDIM];
__device__ float g_mlp [(size_t)MROWS * HID];
__device__ float g_wr  [W_TOT];

// ---------------- helpers ----------------
__device__ __forceinline__ float tf32r(float x) {
    uint32_t u;
    asm("cvt.rna.tf32.f32 %0, %1;" : "=r"(u) : "f"(x));
    return __uint_as_float(u);
}

__device__ __forceinline__ void cp16(void* smem, const void* gmem) {
    uint32_t s = (uint32_t)__cvta_generic_to_shared(smem);
    asm volatile("cp.async.ca.shared.global [%0], [%1], 16;" :: "r"(s), "l"(gmem));
}

__device__ __forceinline__ void mma_tf32(float* d, const uint32_t* a, const uint32_t* b) {
    asm volatile(
        "mma.sync.aligned.m16n8k8.row.col.f32.tf32.tf32.f32 "
        "{%0,%1,%2,%3}, {%4,%5,%6,%7}, {%8,%9}, {%0,%1,%2,%3};"
        : "+f"(d[0]), "+f"(d[1]), "+f"(d[2]), "+f"(d[3])
        : "r"(a[0]), "r"(a[1]), "r"(a[2]), "r"(a[3]), "r"(b[0]), "r"(b[1]));
}

// ---------------- weight rounding ----------------
__global__ void round_kernel(const float* __restrict__ src, float* __restrict__ dst, int n) {
    int i = blockIdx.x * 256 + threadIdx.x;
    if (i < n) dst[i] = tf32r(src[i]);
}

// ---------------- LayerNorm: one warp per 192-wide row (tf32-rounded output) ----------------
__global__ void __launch_bounds__(256) ln_kernel(const float* __restrict__ x,
                                                 const float* __restrict__ g,
                                                 const float* __restrict__ b,
                                                 float* __restrict__ out)
{
    int warp = threadIdx.x >> 5;
    int lane = threadIdx.x & 31;
    long row = (long)blockIdx.x * 8 + warp;
    const float* xr = x + row * CDIM;

    float v[6];
#pragma unroll
    for (int i = 0; i < 6; i++) v[i] = xr[lane + 32 * i];

    float s = 0.f;
#pragma unroll
    for (int i = 0; i < 6; i++) s += v[i];
#pragma unroll
    for (int o = 16; o > 0; o >>= 1) s += __shfl_xor_sync(0xffffffffu, s, o);
    float mean = s * (1.0f / 192.0f);

    float sq = 0.f;
#pragma unroll
    for (int i = 0; i < 6; i++) { float d = v[i] - mean; sq += d * d; }
#pragma unroll
    for (int o = 16; o > 0; o >>= 1) sq += __shfl_xor_sync(0xffffffffu, sq, o);
    float rstd = rsqrtf(sq * (1.0f / 192.0f) + 1e-5f);

    float* orow = out + row * CDIM;
#pragma unroll
    for (int i = 0; i < 6; i++) {
        int c = lane + 32 * i;
        orow[c] = tf32r((v[i] - mean) * rstd * g[c] + b[c]);
    }
}

// ---------------- TF32 tensor-core GEMM ----------------
// C[M,N] = A[M,K] @ B[K,N] + bias (+ epilogue)
// BM=128, BN=64, BK=16. 256 threads = 8 warps (4m x 2n), warp tile 32x32.
// EPI: 0 = bias only, 1 = bias + GELU + tf32 round, 2 = bias + residual add
template <int EPI>
__global__ void __launch_bounds__(256) gemm_tc(const float* __restrict__ A,
                                               const float* __restrict__ B,
                                               const float* __restrict__ bias,
                                               const float* __restrict__ res,
                                               float* __restrict__ C,
                                               int N, int K)
{
    __shared__ float As[2][128 * 20];   // [m][k], stride 20 -> conflict-free frag loads
    __shared__ float Bs[2][16 * 72];    // [k][n], stride 72 -> conflict-free frag loads

    const int tid  = threadIdx.x;
    const int wid  = tid >> 5, lane = tid & 31;
    const int wm   = wid & 3,  wn   = wid >> 2;
    const int g    = lane >> 2, t4  = lane & 3;
    const long m0  = (long)blockIdx.x * 128;
    const int  n0  = blockIdx.y * 64;
    const int  T   = K >> 4;

    float acc[2][4][4];
#pragma unroll
    for (int mi = 0; mi < 2; mi++)
#pragma unroll
        for (int nj = 0; nj < 4; nj++)
#pragma unroll
            for (int r = 0; r < 4; r++) acc[mi][nj][r] = 0.f;

    // producer index precompute
    const int am0 = tid >> 2;            // rows 0..63 (r=0), +64 (r=1)
    const int ak4 = (tid & 3) << 2;
    const int bk  = tid >> 4;
    const int bn4 = (tid & 15) << 2;

    auto load_tile = [&](int t, int buf) {
        int k0 = t << 4;
        cp16(&As[buf][am0 * 20 + ak4],        A + (m0 + am0) * K + k0 + ak4);
        cp16(&As[buf][(am0 + 64) * 20 + ak4], A + (m0 + am0 + 64) * K + k0 + ak4);
        cp16(&Bs[buf][bk * 72 + bn4],         B + (long)(k0 + bk) * N + n0 + bn4);
    };

    load_tile(0, 0);
    asm volatile("cp.async.commit_group;");

    for (int t = 0; t < T; t++) {
        asm volatile("cp.async.wait_group 0;");
        __syncthreads();
        if (t + 1 < T) {
            load_tile(t + 1, (t + 1) & 1);
            asm volatile("cp.async.commit_group;");
        }
        const int buf = t & 1;
#pragma unroll
        for (int ks = 0; ks < 16; ks += 8) {
            uint32_t a[2][4];
#pragma unroll
            for (int mi = 0; mi < 2; mi++) {
                const float* ap = &As[buf][(wm * 32 + mi * 16) * 20 + ks + t4];
                a[mi][0] = __float_as_uint(ap[g * 20]);
                a[mi][1] = __float_as_uint(ap[(g + 8) * 20]);
                a[mi][2] = __float_as_uint(ap[g * 20 + 4]);
                a[mi][3] = __float_as_uint(ap[(g + 8) * 20 + 4]);
            }
            uint32_t b[4][2];
#pragma unroll
            for (int nj = 0; nj < 4; nj++) {
                const float* bp = &Bs[buf][(ks + t4) * 72 + wn * 32 + nj * 8 + g];
                b[nj][0] = __float_as_uint(bp[0]);
                b[nj][1] = __float_as_uint(bp[4 * 72]);
            }
#pragma unroll
            for (int mi = 0; mi < 2; mi++)
#pragma unroll
                for (int nj = 0; nj < 4; nj++)
                    mma_tf32(acc[mi][nj], a[mi], b[nj]);
        }
        __syncthreads();
    }

    // epilogue
#pragma unroll
    for (int mi = 0; mi < 2; mi++) {
#pragma unroll
        for (int half = 0; half < 2; half++) {
            long r = m0 + wm * 32 + mi * 16 + g + half * 8;
#pragma unroll
            for (int nj = 0; nj < 4; nj++) {
                int cb = n0 + wn * 32 + nj * 8 + 2 * t4;
                float o0 = acc[mi][nj][half * 2 + 0] + bias[cb];
                float o1 = acc[mi][nj][half * 2 + 1] + bias[cb + 1];
                if (EPI == 1) {
                    o0 = tf32r(0.5f * o0 * (1.0f + erff(o0 * 0.7071067811865476f)));
                    o1 = tf32r(0.5f * o1 * (1.0f + erff(o1 * 0.7071067811865476f)));
                }
                if (EPI == 2) {
                    const float2 rv = *(const float2*)(res + r * N + cb);
                    o0 += rv.x; o1 += rv.y;
                }
                *(float2*)(C + r * N + cb) = make_float2(o0, o1);
            }
        }
    }
}

// ---------------- Windowed attention: one block per (window, head) ----------------
__global__ void __launch_bounds__(128) attn_kernel(const float* __restrict__ attn_bias)
{
    __shared__ float qs[49 * 33];
    __shared__ float ks[49 * 33];
    __shared__ float vs[49 * 33];
    __shared__ float S[49 * 49];
    __shared__ float bh[49];
    __shared__ int   grow[49];

    int tid = threadIdx.x;
    int wid = blockIdx.x;
    int h   = blockIdx.y;
    int b   = wid >> 6;
    int wr  = wid & 63;
    int wy  = wr >> 3, wx = wr & 7;

    if (tid < 49) {
        int ty = tid / 7, tx = tid - ty * 7;
        grow[tid] = b * 3136 + (wy * 7 + ty) * HW + (wx * 7 + tx);
        bh[tid]   = attn_bias[h * 49 + tid];
    }
    __syncthreads();

    for (int i = tid; i < 49 * 32; i += 128) {
        int t = i >> 5, d = i & 31;
        const float* p = g_qkv + (long)grow[t] * QKVN + h * 96 + d;
        qs[t * 33 + d] = p[0];
        ks[t * 33 + d] = p[32];
        vs[t * 33 + d] = p[64];
    }
    __syncthreads();

    const float scale = 0.17677669529663687f;
    for (int i = tid; i < 2401; i += 128) {
        int n = i / 49, m = i - n * 49;
        float s = 0.f;
#pragma unroll
        for (int d = 0; d < 32; d++) s += qs[n * 33 + d] * ks[m * 33 + d];
        int rn = n / 7, cn = n - rn * 7;
        int rm = m / 7, cm = m - rm * 7;
        int off = abs(rn - rm) * 7 + abs(cn - cm);
        S[i] = s * scale + bh[off];
    }
    __syncthreads();

    if (tid < 49) {
        float mx = -1e30f;
        for (int m = 0; m < 49; m++) mx = fmaxf(mx, S[tid * 49 + m]);
        float sum = 0.f;
        for (int m = 0; m < 49; m++) {
            float e = expf(S[tid * 49 + m] - mx);
            S[tid * 49 + m] = e;
            sum += e;
        }
        float inv = 1.0f / sum;
        for (int m = 0; m < 49; m++) S[tid * 49 + m] *= inv;
    }
    __syncthreads();

    for (int i = tid; i < 49 * 32; i += 128) {
        int n = i >> 5, d = i & 31;
        float s = 0.f;
#pragma unroll
        for (int m = 0; m < 49; m++) s += S[n * 49 + m] * vs[m * 33 + d];
        g_attn[(long)grow[n] * CDIM + h * KD + d] = tf32r(s);
    }
}

// ---------------- depthwise 3x3 conv + BN ----------------
__global__ void __launch_bounds__(192) dwconv_bn_kernel(const float* __restrict__ w,
                                                        const float* __restrict__ g,
                                                        const float* __restrict__ b,
                                                        const float* __restrict__ mean,
                                                        const float* __restrict__ var)
{
    int bl = blockIdx.x;
    int ch = threadIdx.x;
    int bb = bl / 3136;
    int l  = bl - bb * 3136;
    int r  = l / HW, c = l - r * HW;

    float acc = 0.f;
#pragma unroll
    for (int kh = 0; kh < 3; kh++) {
        int rr = r + kh - 1;
        if (rr < 0 || rr >= HW) continue;
#pragma unroll
        for (int kw = 0; kw < 3; kw++) {
            int cc = c + kw - 1;
            if (cc < 0 || cc >= HW) continue;
            acc += g_x1[((long)bb * 3136 + rr * HW + cc) * CDIM + ch] *
                   w[ch * 9 + kh * 3 + kw];
        }
    }
    float inv = rsqrtf(var[ch] + 1e-5f);
    g_x2[(long)bl * CDIM + ch] = (acc - mean[ch]) * g[ch] * inv + b[ch];
}

// ---------------- launch ----------------
extern "C" void kernel_launch(void* const* d_in, const int* in_sizes, int n_in,
                              void* d_out, int out_size)
{
    (void)in_sizes; (void)n_in; (void)out_size;
    const float* x        = (const float*)d_in[0];
    const float* norm1_g  = (const float*)d_in[1];
    const float* norm1_b  = (const float*)d_in[2];
    const float* qkv_w    = (const float*)d_in[3];
    const float* qkv_b    = (const float*)d_in[4];
    const float* attnbias = (const float*)d_in[5];
    const float* proj_w   = (const float*)d_in[6];
    const float* proj_b   = (const float*)d_in[7];
    const float* conv_w   = (const float*)d_in[8];
    const float* bn_g     = (const float*)d_in[9];
    const float* bn_b     = (const float*)d_in[10];
    const float* bn_mean  = (const float*)d_in[11];
    const float* bn_var   = (const float*)d_in[12];
    const float* norm2_g  = (const float*)d_in[13];
    const float* norm2_b  = (const float*)d_in[14];
    const float* fc1_w    = (const float*)d_in[15];
    const float* fc1_b    = (const float*)d_in[16];
    const float* fc2_w    = (const float*)d_in[17];
    const float* fc2_b    = (const float*)d_in[18];
    float* out = (float*)d_out;

    float *p_ln, *p_qkv, *p_attn, *p_x1, *p_x2, *p_mlp, *p_wr;
    cudaGetSymbolAddress((void**)&p_ln,   g_ln);
    cudaGetSymbolAddress((void**)&p_qkv,  g_qkv);
    cudaGetSymbolAddress((void**)&p_attn, g_attn);
    cudaGetSymbolAddress((void**)&p_x1,   g_x1);
    cudaGetSymbolAddress((void**)&p_x2,   g_x2);
    cudaGetSymbolAddress((void**)&p_mlp,  g_mlp);
    cudaGetSymbolAddress((void**)&p_wr,   g_wr);

    // 0) round weights to tf32 (RNA) once per launch
    round_kernel<<<(110592 + 255) / 256, 256>>>(qkv_w,  p_wr + W_QKV,  110592);
    round_kernel<<<(36864  + 255) / 256, 256>>>(proj_w, p_wr + W_PROJ, 36864);
    round_kernel<<<(147456 + 255) / 256, 256>>>(fc1_w,  p_wr + W_FC1,  147456);
    round_kernel<<<(147456 + 255) / 256, 256>>>(fc2_w,  p_wr + W_FC2,  147456);

    // 1) LN1
    ln_kernel<<<MROWS / 8, 256>>>(x, norm1_g, norm1_b, p_ln);
    // 2) QKV GEMM: [M,192] @ [192,576]
    gemm_tc<0><<<dim3(MROWS / 128, QKVN / 64), 256>>>(p_ln, p_wr + W_QKV, qkv_b, nullptr, p_qkv, QKVN, CDIM);
    // 3) windowed attention
    attn_kernel<<<dim3(2048, NHEADS), 128>>>(attnbias);
    // 4) proj GEMM + residual x
    gemm_tc<2><<<dim3(MROWS / 128, CDIM / 64), 256>>>(p_attn, p_wr + W_PROJ, proj_b, x, p_x1, CDIM, CDIM);
    // 5) depthwise conv + BN
    dwconv_bn_kernel<<<MROWS, CDIM>>>(conv_w, bn_g, bn_b, bn_mean, bn_var);
    // 6) LN2
    ln_kernel<<<MROWS / 8, 256>>>(p_x2, norm2_g, norm2_b, p_ln);
    // 7) fc1 GEMM + GELU: [M,192] @ [192,768]
    gemm_tc<1><<<dim3(MROWS / 128, HID / 64), 256>>>(p_ln, p_wr + W_FC1, fc1_b, nullptr, p_mlp, HID, CDIM);
    // 8) fc2 GEMM + residual x2 -> out: [M,768] @ [768,192]
    gemm_tc<2><<<dim3(MROWS / 128, CDIM / 64), 256>>>(p_mlp, p_wr + W_FC2, fc2_b, p_x2, out, CDIM, HID);
}